// round 14
// baseline (speedup 1.0000x reference)
#include <cuda_runtime.h>
#include <cuda_bf16.h>
#include <math.h>

// ---------------------------------------------------------------------------
// GCNEncoder: out = GCN2( relu( GCN1(x) ) )
//   GCNconv(x) = segment_sum( (x@W)[col] * norm ) + b,  norm = dinv[row]*dinv[col]
//   row = concat(edge_index[0], arange(N)) (targets), col = concat(edge_index[1], arange(N))
//
// Strategy:
//   1. degree count (targets) + self loop  -> dinv = rsqrt(deg)
//   2. exclusive prefix sum of deg -> CSR row_ptr (3-kernel scan)
//   3. counting-sort edges by destination into CSR (col, norm); self loop in slot 0
//   4. GEMM1 (fp32 register-tiled 128x64 tile, 8x8 per thread)
//   5. CSR aggregation (warp per node, register accumulation, +b1, relu)
//   6. GEMM2
//   7. CSR aggregation (+b2) -> d_out
// ---------------------------------------------------------------------------

#define N_NODES 100000
#define E_CAP   1800000          // edges + self loops capacity
#define SCAN_B  512
#define SCAN_NBLK ((N_NODES + SCAN_B - 1) / SCAN_B)   // 196

// ---- device scratch (static; no allocation allowed) ----
__device__ int   g_deg[N_NODES];
__device__ float g_dinv[N_NODES];
__device__ int   g_rowptr[N_NODES + 1];
__device__ int   g_cursor[N_NODES];
__device__ int   g_partials[256];
__device__ int   g_poffs[256];
__device__ int   g_csr_col[E_CAP];
__device__ float g_csr_norm[E_CAP];
__device__ float g_h[(size_t)N_NODES * 64];   // GEMM output
__device__ float g_a[(size_t)N_NODES * 64];   // aggregated / layer-2 input

// ---------------------------------------------------------------------------
// preprocessing kernels
// ---------------------------------------------------------------------------
__global__ void k_init_deg() {
    int i = blockIdx.x * blockDim.x + threadIdx.x;
    if (i < N_NODES) g_deg[i] = 1;   // self loop
}

__global__ void k_count_deg(const int* __restrict__ ei, int E) {
    int i = blockIdx.x * blockDim.x + threadIdx.x;
    if (i < E) atomicAdd(&g_deg[ei[i]], 1);   // ei[0..E) = targets (row)
}

// per-block sums of deg (+ dinv)
__global__ void k_reduce_deg() {
    int i = blockIdx.x * SCAN_B + threadIdx.x;
    int v = 0;
    if (i < N_NODES) {
        v = g_deg[i];
        g_dinv[i] = rsqrtf((float)v);
    }
    int lane = threadIdx.x & 31, wid = threadIdx.x >> 5;
    #pragma unroll
    for (int o = 16; o; o >>= 1) v += __shfl_down_sync(0xffffffffu, v, o);
    __shared__ int ws[16];
    if (lane == 0) ws[wid] = v;
    __syncthreads();
    if (threadIdx.x < 16) {
        int s = ws[threadIdx.x];
        #pragma unroll
        for (int o = 8; o; o >>= 1) s += __shfl_down_sync(0xffffu, s, o);
        if (threadIdx.x == 0) g_partials[blockIdx.x] = s;
    }
}

// exclusive scan of block partials (196 values) — 1 block
__global__ void k_scan_partials(int nblk) {
    __shared__ int sh[256];
    int t = threadIdx.x;
    sh[t] = (t < nblk) ? g_partials[t] : 0;
    __syncthreads();
    if (t == 0) {
        int run = 0;
        for (int i = 0; i < nblk; i++) { int v = sh[i]; g_poffs[i] = run; run += v; }
    }
}

// per-block exclusive scan + write row_ptr, cursor, and the self-loop CSR slot
__global__ void k_scan_blocks() {
    int i = blockIdx.x * SCAN_B + threadIdx.x;
    int v = (i < N_NODES) ? g_deg[i] : 0;
    int lane = threadIdx.x & 31, wid = threadIdx.x >> 5;
    int x = v;
    #pragma unroll
    for (int o = 1; o < 32; o <<= 1) {
        int y = __shfl_up_sync(0xffffffffu, x, o);
        if (lane >= o) x += y;
    }
    __shared__ int ws[16];
    if (lane == 31) ws[wid] = x;
    __syncthreads();
    if (wid == 0) {
        int s = (lane < 16) ? ws[lane] : 0;
        #pragma unroll
        for (int o = 1; o < 16; o <<= 1) {
            int y = __shfl_up_sync(0xffffffffu, s, o);
            if (lane >= o) s += y;
        }
        if (lane < 16) ws[lane] = s;
    }
    __syncthreads();
    int incl = x + (wid > 0 ? ws[wid - 1] : 0);
    int excl = incl - v + g_poffs[blockIdx.x];
    if (i < N_NODES) {
        g_rowptr[i] = excl;
        g_cursor[i] = excl + 1;                 // slot 0 = self loop
        g_csr_col[excl]  = i;
        float d = g_dinv[i];
        g_csr_norm[excl] = d * d;
        if (i == N_NODES - 1) g_rowptr[N_NODES] = excl + v;
    }
}

__global__ void k_fill_csr(const int* __restrict__ ei, int E) {
    int i = blockIdx.x * blockDim.x + threadIdx.x;
    if (i < E) {
        int r = ei[i];          // target  (segment id)
        int c = ei[E + i];      // source  (gather id)
        int p = atomicAdd(&g_cursor[r], 1);
        g_csr_col[p]  = c;
        g_csr_norm[p] = g_dinv[r] * g_dinv[c];
    }
}

// ---------------------------------------------------------------------------
// GEMM: C[n,64] = A[n,K] @ W[K,64]   (fp32, 128x64 block tile, 8x8 per thread)
// 128 threads/block: tx = t&7 (8 col groups), ty = t>>3 (16 row groups)
// ---------------------------------------------------------------------------
template <int K>
__global__ void __launch_bounds__(128) k_gemm(const float* __restrict__ A,
                                              const float* __restrict__ W,
                                              float* __restrict__ C, int n) {
    constexpr int BM = 128, BN = 64, BK = 32;
    __shared__ float As[BK][BM];   // transposed: As[k][m]
    __shared__ float Bs[BK][BN];
    int t  = threadIdx.x;
    int tx = t & 7, ty = t >> 3;
    int blockRow = blockIdx.x * BM;
    float acc[8][8] = {};

    for (int kk = 0; kk < K; kk += BK) {
        // A tile: thread t owns row t of the tile, writes transposed (bank-clean)
        {
            int row = blockRow + t;
            if (row < n) {
                const float4* ap = (const float4*)(A + (size_t)row * K + kk);
                #pragma unroll
                for (int i = 0; i < BK / 4; i++) {
                    float4 v = ap[i];
                    As[i * 4 + 0][t] = v.x;
                    As[i * 4 + 1][t] = v.y;
                    As[i * 4 + 2][t] = v.z;
                    As[i * 4 + 3][t] = v.w;
                }
            } else {
                #pragma unroll
                for (int i = 0; i < BK; i++) As[i][t] = 0.f;
            }
        }
        // B tile: contiguous BK*64 floats = 512 float4, 4 per thread
        {
            const float4* wp = (const float4*)(W + (size_t)kk * BN);
            float4* bs = (float4*)&Bs[0][0];
            #pragma unroll
            for (int i = 0; i < 4; i++) bs[t + i * 128] = wp[t + i * 128];
        }
        __syncthreads();

        #pragma unroll
        for (int k = 0; k < BK; k++) {
            float a[8], b[8];
            *(float4*)&a[0] = *(const float4*)&As[k][ty * 8];
            *(float4*)&a[4] = *(const float4*)&As[k][ty * 8 + 4];
            *(float4*)&b[0] = *(const float4*)&Bs[k][tx * 8];
            *(float4*)&b[4] = *(const float4*)&Bs[k][tx * 8 + 4];
            #pragma unroll
            for (int i = 0; i < 8; i++)
                #pragma unroll
                for (int j = 0; j < 8; j++)
                    acc[i][j] = fmaf(a[i], b[j], acc[i][j]);
        }
        __syncthreads();
    }

    #pragma unroll
    for (int i = 0; i < 8; i++) {
        int row = blockRow + ty * 8 + i;
        if (row < n) {
            float4* cp = (float4*)(C + (size_t)row * 64 + tx * 8);
            cp[0] = *(float4*)&acc[i][0];
            cp[1] = *(float4*)&acc[i][4];
        }
    }
}

// ---------------------------------------------------------------------------
// CSR aggregation: one warp per node. lane holds feature pair [2*lane, 2*lane+1]
// out[n] = (relu?)( sum_k norm[k] * H[col[k]] + bias )
// ---------------------------------------------------------------------------
__global__ void __launch_bounds__(256) k_aggregate(const float* __restrict__ H,
                                                   const float* __restrict__ bias,
                                                   float* __restrict__ out,
                                                   int do_relu) {
    int warp = (blockIdx.x * blockDim.x + threadIdx.x) >> 5;
    int lane = threadIdx.x & 31;
    if (warp >= N_NODES) return;

    int s = g_rowptr[warp];
    int e = g_rowptr[warp + 1];
    float ax = 0.f, ay = 0.f;

    int k = s;
    // MLP=4 unroll to hide L2 gather latency (~234 cyc)
    for (; k + 4 <= e; k += 4) {
        int   c0 = g_csr_col[k],   c1 = g_csr_col[k+1];
        int   c2 = g_csr_col[k+2], c3 = g_csr_col[k+3];
        float w0 = g_csr_norm[k],  w1 = g_csr_norm[k+1];
        float w2 = g_csr_norm[k+2],w3 = g_csr_norm[k+3];
        float2 v0 = *(const float2*)(H + (size_t)c0 * 64 + lane * 2);
        float2 v1 = *(const float2*)(H + (size_t)c1 * 64 + lane * 2);
        float2 v2 = *(const float2*)(H + (size_t)c2 * 64 + lane * 2);
        float2 v3 = *(const float2*)(H + (size_t)c3 * 64 + lane * 2);
        ax = fmaf(w0, v0.x, ax); ay = fmaf(w0, v0.y, ay);
        ax = fmaf(w1, v1.x, ax); ay = fmaf(w1, v1.y, ay);
        ax = fmaf(w2, v2.x, ax); ay = fmaf(w2, v2.y, ay);
        ax = fmaf(w3, v3.x, ax); ay = fmaf(w3, v3.y, ay);
    }
    for (; k < e; k++) {
        int   c = g_csr_col[k];
        float w = g_csr_norm[k];
        float2 v = *(const float2*)(H + (size_t)c * 64 + lane * 2);
        ax = fmaf(w, v.x, ax); ay = fmaf(w, v.y, ay);
    }

    float ox = ax + bias[lane * 2];
    float oy = ay + bias[lane * 2 + 1];
    if (do_relu) { ox = fmaxf(ox, 0.f); oy = fmaxf(oy, 0.f); }
    *(float2*)(out + (size_t)warp * 64 + lane * 2) = make_float2(ox, oy);
}

// ---------------------------------------------------------------------------
// launch
// ---------------------------------------------------------------------------
extern "C" void kernel_launch(void* const* d_in, const int* in_sizes, int n_in,
                              void* d_out, int out_size) {
    const float* x   = (const float*)d_in[0];   // [N, 128]
    const int*   ei  = (const int*)  d_in[1];   // [2, E] row-major
    const float* W1  = (const float*)d_in[2];   // [128, 64]
    const float* b1  = (const float*)d_in[3];   // [64]
    const float* W2  = (const float*)d_in[4];   // [64, 64]
    const float* b2  = (const float*)d_in[5];   // [64]
    float*       out = (float*)d_out;           // [N, 64]

    int E = in_sizes[1] / 2;
    if (E + N_NODES > E_CAP) E = E_CAP - N_NODES;   // safety clamp

    float *h_ptr, *a_ptr;
    cudaGetSymbolAddress((void**)&h_ptr, g_h);
    cudaGetSymbolAddress((void**)&a_ptr, g_a);

    const int N = N_NODES;

    // --- build normalization + CSR ---
    k_init_deg<<<(N + 255) / 256, 256>>>();
    k_count_deg<<<(E + 255) / 256, 256>>>(ei, E);
    k_reduce_deg<<<SCAN_NBLK, SCAN_B>>>();
    k_scan_partials<<<1, 256>>>(SCAN_NBLK);
    k_scan_blocks<<<SCAN_NBLK, SCAN_B>>>();
    k_fill_csr<<<(E + 255) / 256, 256>>>(ei, E);

    // --- layer 1 ---
    k_gemm<128><<<(N + 127) / 128, 128>>>(x, W1, h_ptr, N);
    k_aggregate<<<(N * 32 + 255) / 256, 256>>>(h_ptr, b1, a_ptr, 1);

    // --- layer 2 ---
    k_gemm<64><<<(N + 127) / 128, 128>>>(a_ptr, W2, h_ptr, N);
    k_aggregate<<<(N * 32 + 255) / 256, 256>>>(h_ptr, b2, out, 0);
}

// round 15
// speedup vs baseline: 1.0009x; 1.0009x over previous
#include <cuda_runtime.h>
#include <cuda_bf16.h>
#include <math.h>

// ---------------------------------------------------------------------------
// GCNEncoder: out = GCN2( relu( GCN1(x) ) )
//   GCNconv(x) = segment_sum( (x@W)[col] * norm ) + b,  norm = dinv[row]*dinv[col]
//   row = concat(edge_index[0], arange(N)) (targets), col = concat(edge_index[1], arange(N))
//
// Strategy:
//   1. degree count (targets) + self loop  -> dinv = rsqrt(deg)
//   2. exclusive prefix sum of deg -> CSR row_ptr (3-kernel scan)
//   3. counting-sort edges by destination into CSR (col, norm); self loop in slot 0
//   4. GEMM1 (fp32 register-tiled 128x64 tile, 8x8 per thread)
//   5. CSR aggregation (warp per node, register accumulation, +b1, relu)
//   6. GEMM2
//   7. CSR aggregation (+b2) -> d_out
// ---------------------------------------------------------------------------

#define N_NODES 100000
#define E_CAP   1800000          // edges + self loops capacity
#define SCAN_B  512
#define SCAN_NBLK ((N_NODES + SCAN_B - 1) / SCAN_B)   // 196

// ---- device scratch (static; no allocation allowed) ----
__device__ int   g_deg[N_NODES];
__device__ float g_dinv[N_NODES];
__device__ int   g_rowptr[N_NODES + 1];
__device__ int   g_cursor[N_NODES];
__device__ int   g_partials[256];
__device__ int   g_poffs[256];
__device__ int   g_csr_col[E_CAP];
__device__ float g_csr_norm[E_CAP];
__device__ float g_h[(size_t)N_NODES * 64];   // GEMM output
__device__ float g_a[(size_t)N_NODES * 64];   // aggregated / layer-2 input

// ---------------------------------------------------------------------------
// preprocessing kernels
// ---------------------------------------------------------------------------
__global__ void k_init_deg() {
    int i = blockIdx.x * blockDim.x + threadIdx.x;
    if (i < N_NODES) g_deg[i] = 1;   // self loop
}

__global__ void k_count_deg(const int* __restrict__ ei, int E) {
    int i = blockIdx.x * blockDim.x + threadIdx.x;
    if (i < E) atomicAdd(&g_deg[ei[i]], 1);   // ei[0..E) = targets (row)
}

// per-block sums of deg (+ dinv)
__global__ void k_reduce_deg() {
    int i = blockIdx.x * SCAN_B + threadIdx.x;
    int v = 0;
    if (i < N_NODES) {
        v = g_deg[i];
        g_dinv[i] = rsqrtf((float)v);
    }
    int lane = threadIdx.x & 31, wid = threadIdx.x >> 5;
    #pragma unroll
    for (int o = 16; o; o >>= 1) v += __shfl_down_sync(0xffffffffu, v, o);
    __shared__ int ws[16];
    if (lane == 0) ws[wid] = v;
    __syncthreads();
    if (threadIdx.x < 16) {
        int s = ws[threadIdx.x];
        #pragma unroll
        for (int o = 8; o; o >>= 1) s += __shfl_down_sync(0xffffu, s, o);
        if (threadIdx.x == 0) g_partials[blockIdx.x] = s;
    }
}

// exclusive scan of block partials (196 values) — 1 block
__global__ void k_scan_partials(int nblk) {
    __shared__ int sh[256];
    int t = threadIdx.x;
    sh[t] = (t < nblk) ? g_partials[t] : 0;
    __syncthreads();
    if (t == 0) {
        int run = 0;
        for (int i = 0; i < nblk; i++) { int v = sh[i]; g_poffs[i] = run; run += v; }
    }
}

// per-block exclusive scan + write row_ptr, cursor, and the self-loop CSR slot
__global__ void k_scan_blocks() {
    int i = blockIdx.x * SCAN_B + threadIdx.x;
    int v = (i < N_NODES) ? g_deg[i] : 0;
    int lane = threadIdx.x & 31, wid = threadIdx.x >> 5;
    int x = v;
    #pragma unroll
    for (int o = 1; o < 32; o <<= 1) {
        int y = __shfl_up_sync(0xffffffffu, x, o);
        if (lane >= o) x += y;
    }
    __shared__ int ws[16];
    if (lane == 31) ws[wid] = x;
    __syncthreads();
    if (wid == 0) {
        int s = (lane < 16) ? ws[lane] : 0;
        #pragma unroll
        for (int o = 1; o < 16; o <<= 1) {
            int y = __shfl_up_sync(0xffffffffu, s, o);
            if (lane >= o) s += y;
        }
        if (lane < 16) ws[lane] = s;
    }
    __syncthreads();
    int incl = x + (wid > 0 ? ws[wid - 1] : 0);
    int excl = incl - v + g_poffs[blockIdx.x];
    if (i < N_NODES) {
        g_rowptr[i] = excl;
        g_cursor[i] = excl + 1;                 // slot 0 = self loop
        g_csr_col[excl]  = i;
        float d = g_dinv[i];
        g_csr_norm[excl] = d * d;
        if (i == N_NODES - 1) g_rowptr[N_NODES] = excl + v;
    }
}

__global__ void k_fill_csr(const int* __restrict__ ei, int E) {
    int i = blockIdx.x * blockDim.x + threadIdx.x;
    if (i < E) {
        int r = ei[i];          // target  (segment id)
        int c = ei[E + i];      // source  (gather id)
        int p = atomicAdd(&g_cursor[r], 1);
        g_csr_col[p]  = c;
        g_csr_norm[p] = g_dinv[r] * g_dinv[c];
    }
}

// ---------------------------------------------------------------------------
// GEMM: C[n,64] = A[n,K] @ W[K,64]   (fp32, 128x64 block tile, 8x8 per thread)
// 128 threads/block: tx = t&7 (8 col groups), ty = t>>3 (16 row groups)
// ---------------------------------------------------------------------------
template <int K>
__global__ void __launch_bounds__(128) k_gemm(const float* __restrict__ A,
                                              const float* __restrict__ W,
                                              float* __restrict__ C, int n) {
    constexpr int BM = 128, BN = 64, BK = 32;
    __shared__ float As[BK][BM];   // transposed: As[k][m]
    __shared__ float Bs[BK][BN];
    int t  = threadIdx.x;
    int tx = t & 7, ty = t >> 3;
    int blockRow = blockIdx.x * BM;
    float acc[8][8] = {};

    for (int kk = 0; kk < K; kk += BK) {
        // A tile: thread t owns row t of the tile, writes transposed (bank-clean)
        {
            int row = blockRow + t;
            if (row < n) {
                const float4* ap = (const float4*)(A + (size_t)row * K + kk);
                #pragma unroll
                for (int i = 0; i < BK / 4; i++) {
                    float4 v = ap[i];
                    As[i * 4 + 0][t] = v.x;
                    As[i * 4 + 1][t] = v.y;
                    As[i * 4 + 2][t] = v.z;
                    As[i * 4 + 3][t] = v.w;
                }
            } else {
                #pragma unroll
                for (int i = 0; i < BK; i++) As[i][t] = 0.f;
            }
        }
        // B tile: contiguous BK*64 floats = 512 float4, 4 per thread
        {
            const float4* wp = (const float4*)(W + (size_t)kk * BN);
            float4* bs = (float4*)&Bs[0][0];
            #pragma unroll
            for (int i = 0; i < 4; i++) bs[t + i * 128] = wp[t + i * 128];
        }
        __syncthreads();

        #pragma unroll
        for (int k = 0; k < BK; k++) {
            float a[8], b[8];
            *(float4*)&a[0] = *(const float4*)&As[k][ty * 8];
            *(float4*)&a[4] = *(const float4*)&As[k][ty * 8 + 4];
            *(float4*)&b[0] = *(const float4*)&Bs[k][tx * 8];
            *(float4*)&b[4] = *(const float4*)&Bs[k][tx * 8 + 4];
            #pragma unroll
            for (int i = 0; i < 8; i++)
                #pragma unroll
                for (int j = 0; j < 8; j++)
                    acc[i][j] = fmaf(a[i], b[j], acc[i][j]);
        }
        __syncthreads();
    }

    #pragma unroll
    for (int i = 0; i < 8; i++) {
        int row = blockRow + ty * 8 + i;
        if (row < n) {
            float4* cp = (float4*)(C + (size_t)row * 64 + tx * 8);
            cp[0] = *(float4*)&acc[i][0];
            cp[1] = *(float4*)&acc[i][4];
        }
    }
}

// ---------------------------------------------------------------------------
// CSR aggregation: one warp per node. lane holds feature pair [2*lane, 2*lane+1]
// out[n] = (relu?)( sum_k norm[k] * H[col[k]] + bias )
// ---------------------------------------------------------------------------
__global__ void __launch_bounds__(256) k_aggregate(const float* __restrict__ H,
                                                   const float* __restrict__ bias,
                                                   float* __restrict__ out,
                                                   int do_relu) {
    int warp = (blockIdx.x * blockDim.x + threadIdx.x) >> 5;
    int lane = threadIdx.x & 31;
    if (warp >= N_NODES) return;

    int s = g_rowptr[warp];
    int e = g_rowptr[warp + 1];
    float ax = 0.f, ay = 0.f;

    int k = s;
    // MLP=4 unroll to hide L2 gather latency (~234 cyc)
    for (; k + 4 <= e; k += 4) {
        int   c0 = g_csr_col[k],   c1 = g_csr_col[k+1];
        int   c2 = g_csr_col[k+2], c3 = g_csr_col[k+3];
        float w0 = g_csr_norm[k],  w1 = g_csr_norm[k+1];
        float w2 = g_csr_norm[k+2],w3 = g_csr_norm[k+3];
        float2 v0 = *(const float2*)(H + (size_t)c0 * 64 + lane * 2);
        float2 v1 = *(const float2*)(H + (size_t)c1 * 64 + lane * 2);
        float2 v2 = *(const float2*)(H + (size_t)c2 * 64 + lane * 2);
        float2 v3 = *(const float2*)(H + (size_t)c3 * 64 + lane * 2);
        ax = fmaf(w0, v0.x, ax); ay = fmaf(w0, v0.y, ay);
        ax = fmaf(w1, v1.x, ax); ay = fmaf(w1, v1.y, ay);
        ax = fmaf(w2, v2.x, ax); ay = fmaf(w2, v2.y, ay);
        ax = fmaf(w3, v3.x, ax); ay = fmaf(w3, v3.y, ay);
    }
    for (; k < e; k++) {
        int   c = g_csr_col[k];
        float w = g_csr_norm[k];
        float2 v = *(const float2*)(H + (size_t)c * 64 + lane * 2);
        ax = fmaf(w, v.x, ax); ay = fmaf(w, v.y, ay);
    }

    float ox = ax + bias[lane * 2];
    float oy = ay + bias[lane * 2 + 1];
    if (do_relu) { ox = fmaxf(ox, 0.f); oy = fmaxf(oy, 0.f); }
    *(float2*)(out + (size_t)warp * 64 + lane * 2) = make_float2(ox, oy);
}

// ---------------------------------------------------------------------------
// launch
// ---------------------------------------------------------------------------
extern "C" void kernel_launch(void* const* d_in, const int* in_sizes, int n_in,
                              void* d_out, int out_size) {
    const float* x   = (const float*)d_in[0];   // [N, 128]
    const int*   ei  = (const int*)  d_in[1];   // [2, E] row-major
    const float* W1  = (const float*)d_in[2];   // [128, 64]
    const float* b1  = (const float*)d_in[3];   // [64]
    const float* W2  = (const float*)d_in[4];   // [64, 64]
    const float* b2  = (const float*)d_in[5];   // [64]
    float*       out = (float*)d_out;           // [N, 64]

    int E = in_sizes[1] / 2;
    if (E + N_NODES > E_CAP) E = E_CAP - N_NODES;   // safety clamp

    float *h_ptr, *a_ptr;
    cudaGetSymbolAddress((void**)&h_ptr, g_h);
    cudaGetSymbolAddress((void**)&a_ptr, g_a);

    const int N = N_NODES;

    // --- build normalization + CSR ---
    k_init_deg<<<(N + 255) / 256, 256>>>();
    k_count_deg<<<(E + 255) / 256, 256>>>(ei, E);
    k_reduce_deg<<<SCAN_NBLK, SCAN_B>>>();
    k_scan_partials<<<1, 256>>>(SCAN_NBLK);
    k_scan_blocks<<<SCAN_NBLK, SCAN_B>>>();
    k_fill_csr<<<(E + 255) / 256, 256>>>(ei, E);

    // --- layer 1 ---
    k_gemm<128><<<(N + 127) / 128, 128>>>(x, W1, h_ptr, N);
    k_aggregate<<<(N * 32 + 255) / 256, 256>>>(h_ptr, b1, a_ptr, 1);

    // --- layer 2 ---
    k_gemm<64><<<(N + 127) / 128, 128>>>(a_ptr, W2, h_ptr, N);
    k_aggregate<<<(N * 32 + 255) / 256, 256>>>(h_ptr, b2, out, 0);
}

// round 16
// speedup vs baseline: 1.0016x; 1.0007x over previous
#include <cuda_runtime.h>
#include <cuda_bf16.h>
#include <math.h>

// ---------------------------------------------------------------------------
// GCNEncoder: out = GCN2( relu( GCN1(x) ) )
//   GCNconv(x) = segment_sum( (x@W)[col] * norm ) + b,  norm = dinv[row]*dinv[col]
//   row = concat(edge_index[0], arange(N)) (targets), col = concat(edge_index[1], arange(N))
//
// Strategy:
//   1. degree count (targets) + self loop  -> dinv = rsqrt(deg)
//   2. exclusive prefix sum of deg -> CSR row_ptr (3-kernel scan)
//   3. counting-sort edges by destination into CSR (col, norm); self loop in slot 0
//   4. GEMM1 (fp32 register-tiled 128x64 tile, 8x8 per thread)
//   5. CSR aggregation (warp per node, register accumulation, +b1, relu)
//   6. GEMM2
//   7. CSR aggregation (+b2) -> d_out
// ---------------------------------------------------------------------------

#define N_NODES 100000
#define E_CAP   1800000          // edges + self loops capacity
#define SCAN_B  512
#define SCAN_NBLK ((N_NODES + SCAN_B - 1) / SCAN_B)   // 196

// ---- device scratch (static; no allocation allowed) ----
__device__ int   g_deg[N_NODES];
__device__ float g_dinv[N_NODES];
__device__ int   g_rowptr[N_NODES + 1];
__device__ int   g_cursor[N_NODES];
__device__ int   g_partials[256];
__device__ int   g_poffs[256];
__device__ int   g_csr_col[E_CAP];
__device__ float g_csr_norm[E_CAP];
__device__ float g_h[(size_t)N_NODES * 64];   // GEMM output
__device__ float g_a[(size_t)N_NODES * 64];   // aggregated / layer-2 input

// ---------------------------------------------------------------------------
// preprocessing kernels
// ---------------------------------------------------------------------------
__global__ void k_init_deg() {
    int i = blockIdx.x * blockDim.x + threadIdx.x;
    if (i < N_NODES) g_deg[i] = 1;   // self loop
}

__global__ void k_count_deg(const int* __restrict__ ei, int E) {
    int i = blockIdx.x * blockDim.x + threadIdx.x;
    if (i < E) atomicAdd(&g_deg[ei[i]], 1);   // ei[0..E) = targets (row)
}

// per-block sums of deg (+ dinv)
__global__ void k_reduce_deg() {
    int i = blockIdx.x * SCAN_B + threadIdx.x;
    int v = 0;
    if (i < N_NODES) {
        v = g_deg[i];
        g_dinv[i] = rsqrtf((float)v);
    }
    int lane = threadIdx.x & 31, wid = threadIdx.x >> 5;
    #pragma unroll
    for (int o = 16; o; o >>= 1) v += __shfl_down_sync(0xffffffffu, v, o);
    __shared__ int ws[16];
    if (lane == 0) ws[wid] = v;
    __syncthreads();
    if (threadIdx.x < 16) {
        int s = ws[threadIdx.x];
        #pragma unroll
        for (int o = 8; o; o >>= 1) s += __shfl_down_sync(0xffffu, s, o);
        if (threadIdx.x == 0) g_partials[blockIdx.x] = s;
    }
}

// exclusive scan of block partials (196 values) — 1 block
__global__ void k_scan_partials(int nblk) {
    __shared__ int sh[256];
    int t = threadIdx.x;
    sh[t] = (t < nblk) ? g_partials[t] : 0;
    __syncthreads();
    if (t == 0) {
        int run = 0;
        for (int i = 0; i < nblk; i++) { int v = sh[i]; g_poffs[i] = run; run += v; }
    }
}

// per-block exclusive scan + write row_ptr, cursor, and the self-loop CSR slot
__global__ void k_scan_blocks() {
    int i = blockIdx.x * SCAN_B + threadIdx.x;
    int v = (i < N_NODES) ? g_deg[i] : 0;
    int lane = threadIdx.x & 31, wid = threadIdx.x >> 5;
    int x = v;
    #pragma unroll
    for (int o = 1; o < 32; o <<= 1) {
        int y = __shfl_up_sync(0xffffffffu, x, o);
        if (lane >= o) x += y;
    }
    __shared__ int ws[16];
    if (lane == 31) ws[wid] = x;
    __syncthreads();
    if (wid == 0) {
        int s = (lane < 16) ? ws[lane] : 0;
        #pragma unroll
        for (int o = 1; o < 16; o <<= 1) {
            int y = __shfl_up_sync(0xffffffffu, s, o);
            if (lane >= o) s += y;
        }
        if (lane < 16) ws[lane] = s;
    }
    __syncthreads();
    int incl = x + (wid > 0 ? ws[wid - 1] : 0);
    int excl = incl - v + g_poffs[blockIdx.x];
    if (i < N_NODES) {
        g_rowptr[i] = excl;
        g_cursor[i] = excl + 1;                 // slot 0 = self loop
        g_csr_col[excl]  = i;
        float d = g_dinv[i];
        g_csr_norm[excl] = d * d;
        if (i == N_NODES - 1) g_rowptr[N_NODES] = excl + v;
    }
}

__global__ void k_fill_csr(const int* __restrict__ ei, int E) {
    int i = blockIdx.x * blockDim.x + threadIdx.x;
    if (i < E) {
        int r = ei[i];          // target  (segment id)
        int c = ei[E + i];      // source  (gather id)
        int p = atomicAdd(&g_cursor[r], 1);
        g_csr_col[p]  = c;
        g_csr_norm[p] = g_dinv[r] * g_dinv[c];
    }
}

// ---------------------------------------------------------------------------
// GEMM: C[n,64] = A[n,K] @ W[K,64]   (fp32, 128x64 block tile, 8x8 per thread)
// 128 threads/block: tx = t&7 (8 col groups), ty = t>>3 (16 row groups)
// ---------------------------------------------------------------------------
template <int K>
__global__ void __launch_bounds__(128) k_gemm(const float* __restrict__ A,
                                              const float* __restrict__ W,
                                              float* __restrict__ C, int n) {
    constexpr int BM = 128, BN = 64, BK = 32;
    __shared__ float As[BK][BM];   // transposed: As[k][m]
    __shared__ float Bs[BK][BN];
    int t  = threadIdx.x;
    int tx = t & 7, ty = t >> 3;
    int blockRow = blockIdx.x * BM;
    float acc[8][8] = {};

    for (int kk = 0; kk < K; kk += BK) {
        // A tile: thread t owns row t of the tile, writes transposed (bank-clean)
        {
            int row = blockRow + t;
            if (row < n) {
                const float4* ap = (const float4*)(A + (size_t)row * K + kk);
                #pragma unroll
                for (int i = 0; i < BK / 4; i++) {
                    float4 v = ap[i];
                    As[i * 4 + 0][t] = v.x;
                    As[i * 4 + 1][t] = v.y;
                    As[i * 4 + 2][t] = v.z;
                    As[i * 4 + 3][t] = v.w;
                }
            } else {
                #pragma unroll
                for (int i = 0; i < BK; i++) As[i][t] = 0.f;
            }
        }
        // B tile: contiguous BK*64 floats = 512 float4, 4 per thread
        {
            const float4* wp = (const float4*)(W + (size_t)kk * BN);
            float4* bs = (float4*)&Bs[0][0];
            #pragma unroll
            for (int i = 0; i < 4; i++) bs[t + i * 128] = wp[t + i * 128];
        }
        __syncthreads();

        #pragma unroll
        for (int k = 0; k < BK; k++) {
            float a[8], b[8];
            *(float4*)&a[0] = *(const float4*)&As[k][ty * 8];
            *(float4*)&a[4] = *(const float4*)&As[k][ty * 8 + 4];
            *(float4*)&b[0] = *(const float4*)&Bs[k][tx * 8];
            *(float4*)&b[4] = *(const float4*)&Bs[k][tx * 8 + 4];
            #pragma unroll
            for (int i = 0; i < 8; i++)
                #pragma unroll
                for (int j = 0; j < 8; j++)
                    acc[i][j] = fmaf(a[i], b[j], acc[i][j]);
        }
        __syncthreads();
    }

    #pragma unroll
    for (int i = 0; i < 8; i++) {
        int row = blockRow + ty * 8 + i;
        if (row < n) {
            float4* cp = (float4*)(C + (size_t)row * 64 + tx * 8);
            cp[0] = *(float4*)&acc[i][0];
            cp[1] = *(float4*)&acc[i][4];
        }
    }
}

// ---------------------------------------------------------------------------
// CSR aggregation: one warp per node. lane holds feature pair [2*lane, 2*lane+1]
// out[n] = (relu?)( sum_k norm[k] * H[col[k]] + bias )
// ---------------------------------------------------------------------------
__global__ void __launch_bounds__(256) k_aggregate(const float* __restrict__ H,
                                                   const float* __restrict__ bias,
                                                   float* __restrict__ out,
                                                   int do_relu) {
    int warp = (blockIdx.x * blockDim.x + threadIdx.x) >> 5;
    int lane = threadIdx.x & 31;
    if (warp >= N_NODES) return;

    int s = g_rowptr[warp];
    int e = g_rowptr[warp + 1];
    float ax = 0.f, ay = 0.f;

    int k = s;
    // MLP=4 unroll to hide L2 gather latency (~234 cyc)
    for (; k + 4 <= e; k += 4) {
        int   c0 = g_csr_col[k],   c1 = g_csr_col[k+1];
        int   c2 = g_csr_col[k+2], c3 = g_csr_col[k+3];
        float w0 = g_csr_norm[k],  w1 = g_csr_norm[k+1];
        float w2 = g_csr_norm[k+2],w3 = g_csr_norm[k+3];
        float2 v0 = *(const float2*)(H + (size_t)c0 * 64 + lane * 2);
        float2 v1 = *(const float2*)(H + (size_t)c1 * 64 + lane * 2);
        float2 v2 = *(const float2*)(H + (size_t)c2 * 64 + lane * 2);
        float2 v3 = *(const float2*)(H + (size_t)c3 * 64 + lane * 2);
        ax = fmaf(w0, v0.x, ax); ay = fmaf(w0, v0.y, ay);
        ax = fmaf(w1, v1.x, ax); ay = fmaf(w1, v1.y, ay);
        ax = fmaf(w2, v2.x, ax); ay = fmaf(w2, v2.y, ay);
        ax = fmaf(w3, v3.x, ax); ay = fmaf(w3, v3.y, ay);
    }
    for (; k < e; k++) {
        int   c = g_csr_col[k];
        float w = g_csr_norm[k];
        float2 v = *(const float2*)(H + (size_t)c * 64 + lane * 2);
        ax = fmaf(w, v.x, ax); ay = fmaf(w, v.y, ay);
    }

    float ox = ax + bias[lane * 2];
    float oy = ay + bias[lane * 2 + 1];
    if (do_relu) { ox = fmaxf(ox, 0.f); oy = fmaxf(oy, 0.f); }
    *(float2*)(out + (size_t)warp * 64 + lane * 2) = make_float2(ox, oy);
}

// ---------------------------------------------------------------------------
// launch
// ---------------------------------------------------------------------------
extern "C" void kernel_launch(void* const* d_in, const int* in_sizes, int n_in,
                              void* d_out, int out_size) {
    const float* x   = (const float*)d_in[0];   // [N, 128]
    const int*   ei  = (const int*)  d_in[1];   // [2, E] row-major
    const float* W1  = (const float*)d_in[2];   // [128, 64]
    const float* b1  = (const float*)d_in[3];   // [64]
    const float* W2  = (const float*)d_in[4];   // [64, 64]
    const float* b2  = (const float*)d_in[5];   // [64]
    float*       out = (float*)d_out;           // [N, 64]

    int E = in_sizes[1] / 2;
    if (E + N_NODES > E_CAP) E = E_CAP - N_NODES;   // safety clamp

    float *h_ptr, *a_ptr;
    cudaGetSymbolAddress((void**)&h_ptr, g_h);
    cudaGetSymbolAddress((void**)&a_ptr, g_a);

    const int N = N_NODES;

    // --- build normalization + CSR ---
    k_init_deg<<<(N + 255) / 256, 256>>>();
    k_count_deg<<<(E + 255) / 256, 256>>>(ei, E);
    k_reduce_deg<<<SCAN_NBLK, SCAN_B>>>();
    k_scan_partials<<<1, 256>>>(SCAN_NBLK);
    k_scan_blocks<<<SCAN_NBLK, SCAN_B>>>();
    k_fill_csr<<<(E + 255) / 256, 256>>>(ei, E);

    // --- layer 1 ---
    k_gemm<128><<<(N + 127) / 128, 128>>>(x, W1, h_ptr, N);
    k_aggregate<<<(N * 32 + 255) / 256, 256>>>(h_ptr, b1, a_ptr, 1);

    // --- layer 2 ---
    k_gemm<64><<<(N + 127) / 128, 128>>>(a_ptr, W2, h_ptr, N);
    k_aggregate<<<(N * 32 + 255) / 256, 256>>>(h_ptr, b2, out, 0);
}